// round 7
// baseline (speedup 1.0000x reference)
#include <cuda_runtime.h>
#include <math.h>

#define B 64
#define P 8732
#define NOBJ 16
#define NC 81
#define THRESH 0.5f
#define RPB 128                 // conf rows per block in k_main
#define TPB 256                 // threads per block in k_main (2 per row)
#define CPB 69                  // ceil(P/RPB)
#define NPART (B*CPB)

#define PPB 35                  // per-prior blocks per batch: ceil(8732/256)
#define TSL 8                   // truth-slice blocks per batch
#define SLICE 1092              // ceil(P/TSL)
#define NBX (PPB + TSL)

// ---------------- scratch (device globals; no allocs allowed) ----------------
__device__ float              g_overlap[B*P];
__device__ int                g_tidx[B*P];
__device__ float              g_mine[B*P];
__device__ unsigned long long g_bestprior[B*NOBJ];   // zero at load; k_force restores zeros

__device__ float g_part_lossl[NPART];
__device__ float g_part_lcpos[NPART];
__device__ int   g_part_npos[NPART];

__device__ float g_lossl_b[B];
__device__ float g_lossc_b[B];
__device__ int   g_npos_b[B];

__device__ __forceinline__ float smooth_l1(float x) {
    float ax = fabsf(x);
    return (ax < 1.0f) ? 0.5f * x * x : ax - 0.5f;
}

__device__ __forceinline__ int warp_suffix(int x, int lane) {
    #pragma unroll
    for (int s = 1; s < 32; s <<= 1) {
        int v = __shfl_down_sync(0xffffffffu, x, s);
        if (lane + s < 32) x += v;
    }
    return x;   // x[lane] = sum_{j>=lane} input[j]
}

// ---------------- kernel 1: matching ----------------
// grid (NBX, B), block 256.
//  bx < PPB  : per-prior best-truth argmax (thread per prior)
//  bx >= PPB : per-truth best-prior argmax (warp per 2 truths over a P-slice)
__global__ void k_match(const float* __restrict__ priors,
                        const float* __restrict__ targets) {
    int b  = blockIdx.y;
    int bx = blockIdx.x;
    int tid = threadIdx.x;
    int lane = tid & 31;
    int warp = tid >> 5;

    __shared__ float s_t[NOBJ * 5];
    if (tid < NOBJ * 5) s_t[tid] = targets[b * NOBJ * 5 + tid];
    __syncthreads();

    if (bx < PPB) {
        int p = bx * 256 + tid;
        if (p >= P) return;
        float4 pr = *(const float4*)(priors + p * 4);
        float px1 = pr.x - pr.z * 0.5f, py1 = pr.y - pr.w * 0.5f;
        float px2 = pr.x + pr.z * 0.5f, py2 = pr.y + pr.w * 0.5f;
        float pa  = (px2 - px1) * (py2 - py1);

        float bestv = -1.0f; int besti = 0;
        #pragma unroll
        for (int t = 0; t < NOBJ; t++) {
            float tx1 = s_t[t*5+0], ty1 = s_t[t*5+1], tx2 = s_t[t*5+2], ty2 = s_t[t*5+3];
            float ix1 = fmaxf(tx1, px1), iy1 = fmaxf(ty1, py1);
            float ix2 = fminf(tx2, px2), iy2 = fminf(ty2, py2);
            float iw = fmaxf(ix2 - ix1, 0.f), ih = fmaxf(iy2 - iy1, 0.f);
            float inter = iw * ih;
            float ta = (tx2 - tx1) * (ty2 - ty1);
            float iou = inter / (ta + pa - inter);
            if (iou > bestv) { bestv = iou; besti = t; }
        }
        g_overlap[b * P + p] = bestv;
        g_tidx[b * P + p]    = besti;
    } else {
        int ts = bx - PPB;
        int p_lo = ts * SLICE;
        int p_hi = min(P, p_lo + SLICE);

        #pragma unroll
        for (int r = 0; r < 2; r++) {
            int t = warp * 2 + r;
            float tx1 = s_t[t*5+0], ty1 = s_t[t*5+1], tx2 = s_t[t*5+2], ty2 = s_t[t*5+3];
            float ta = (tx2 - tx1) * (ty2 - ty1);

            unsigned long long key = 0ULL;
            for (int p = p_lo + lane; p < p_hi; p += 32) {
                float4 pr = *(const float4*)(priors + p * 4);
                float px1 = pr.x - pr.z * 0.5f, py1 = pr.y - pr.w * 0.5f;
                float px2 = pr.x + pr.z * 0.5f, py2 = pr.y + pr.w * 0.5f;
                float pa  = (px2 - px1) * (py2 - py1);
                float ix1 = fmaxf(tx1, px1), iy1 = fmaxf(ty1, py1);
                float ix2 = fminf(tx2, px2), iy2 = fminf(ty2, py2);
                float iw = fmaxf(ix2 - ix1, 0.f), ih = fmaxf(iy2 - iy1, 0.f);
                float inter = iw * ih;
                float iou = inter / (ta + pa - inter);
                unsigned long long k =
                    ((((unsigned long long)__float_as_uint(iou)) << 32) |
                     (unsigned long long)(0xFFFFFFFFu - (unsigned)p));
                if (k > key) key = k;
            }
            #pragma unroll
            for (int s = 16; s > 0; s >>= 1) {
                unsigned long long o = __shfl_xor_sync(0xffffffffu, key, s);
                if (o > key) key = o;
            }
            if (lane == 0) atomicMax(&g_bestprior[b * NOBJ + t], key);
        }
    }
}

// ---------------- kernel 2: force best-prior matches + reset keys ------------
__global__ void k_force() {
    int b = threadIdx.x;
    if (b < B) {
        for (int j = 0; j < NOBJ; j++) {
            unsigned long long key = g_bestprior[b * NOBJ + j];
            g_bestprior[b * NOBJ + j] = 0ULL;   // restore for next graph replay
            unsigned p = 0xFFFFFFFFu - (unsigned)(key & 0xFFFFFFFFull);
            g_overlap[b * P + p] = 2.0f;
            g_tidx[b * P + p]    = j;
        }
    }
}

// ---------------- kernel 3: main heavy kernel --------------------------------
// 256 threads, 128 rows/block; 2 threads per row; fully-unrolled f4 staging.
__global__ void __launch_bounds__(TPB) k_main(const float* __restrict__ loc,
                                              const float* __restrict__ conf,
                                              const float* __restrict__ priors,
                                              const float* __restrict__ targets) {
    int blk = blockIdx.x;
    int b   = blk / CPB;
    int c   = blk % CPB;
    int p0  = c * RPB;
    int nrows = (p0 + RPB <= P) ? RPB : (P - p0);

    __shared__ float s_conf[RPB * NC];      // 41472 B
    __shared__ float s_ll[8], s_lc[8];
    __shared__ int   s_np[8];

    int tid = threadIdx.x;

    // (b*P+p0)*NC divisible by 4; fully unrolled -> high MLP
    const float4* base4 = (const float4*)(conf + ((size_t)b * P + p0) * NC);
    float4* s4 = (float4*)s_conf;
    if (nrows == RPB) {
        // 128*81/4 = 2592 = 10*256 + 32
        #pragma unroll
        for (int j = 0; j < 10; j++)
            s4[tid + j * TPB] = __ldg(base4 + tid + j * TPB);
        if (tid < 32)
            s4[2560 + tid] = __ldg(base4 + 2560 + tid);
    } else {
        int n4 = nrows * NC / 4;            // nrows*81 divisible by 4 (nrows=28)
        for (int i = tid; i < n4; i += TPB)
            s4[i] = __ldg(base4 + i);
    }
    __syncthreads();

    float lossl = 0.f, lcpos = 0.f; int np = 0;

    int r = tid >> 1;          // row 0..127
    int h = tid & 1;           // half
    bool act = (r < nrows);

    // partial exp-sum: h=0 -> classes 0..40, h=1 -> 41..80
    float sum = 0.f;
    if (act) {
        const float* row = s_conf + r * NC;
        if (h == 0) {
            #pragma unroll
            for (int j = 0; j < 41; j++) sum += __expf(row[j]);
        } else {
            #pragma unroll
            for (int j = 41; j < 81; j++) sum += __expf(row[j]);
        }
    }
    // UNCONDITIONAL pair exchange (fixes R5 deadlock in the tail block)
    sum += __shfl_xor_sync(0xffffffffu, sum, 1);

    if (act && h == 0) {
        const float* row = s_conf + r * NC;
        int p = p0 + r;
        float lse = __logf(sum);

        float ov = g_overlap[b * P + p];
        int   t  = g_tidx[b * P + p];
        bool  pos = (ov >= THRESH);
        int   ct = 0;
        if (pos) ct = (int)__ldg(&targets[(b * NOBJ + t) * 5 + 4]) + 1;

        float lc = lse - row[ct];
        g_mine[b * P + p] = pos ? 0.f : lc;

        if (pos) {
            np = 1; lcpos = lc;
            float4 pr = *(const float4*)(priors + p * 4);
            const float* tr = targets + (b * NOBJ + t) * 5;
            float mx1 = tr[0], my1 = tr[1], mx2 = tr[2], my2 = tr[3];
            float gcx = ((mx1 + mx2) * 0.5f - pr.x) / (0.1f * pr.z);
            float gcy = ((my1 + my2) * 0.5f - pr.y) / (0.1f * pr.w);
            float gw  = __logf((mx2 - mx1) / pr.z) * 5.0f;
            float gh  = __logf((my2 - my1) / pr.w) * 5.0f;
            float4 ld = *(const float4*)(loc + ((size_t)b * P + p) * 4);
            lossl = smooth_l1(ld.x - gcx) + smooth_l1(ld.y - gcy)
                  + smooth_l1(ld.z - gw)  + smooth_l1(ld.w - gh);
        }
    }

    int lane = tid & 31, warp = tid >> 5;
    #pragma unroll
    for (int s = 16; s > 0; s >>= 1) {
        lossl += __shfl_xor_sync(0xffffffffu, lossl, s);
        lcpos += __shfl_xor_sync(0xffffffffu, lcpos, s);
        np    += __shfl_xor_sync(0xffffffffu, np, s);
    }
    if (lane == 0) { s_ll[warp] = lossl; s_lc[warp] = lcpos; s_np[warp] = np; }
    __syncthreads();
    if (tid == 0) {
        float a = 0.f, bb = 0.f; int n = 0;
        #pragma unroll
        for (int w = 0; w < 8; w++) { a += s_ll[w]; bb += s_lc[w]; n += s_np[w]; }
        g_part_lossl[blk] = a;
        g_part_lcpos[blk] = bb;
        g_part_npos[blk]  = n;
    }
}

// ---------------- kernel 4: per-batch reduce + hard-negative mining ----------
// grid B, block 1024. 3-level histogram top-k, warp-aggregated atomics.
__global__ void __launch_bounds__(1024) k_negred() {
    int b = blockIdx.x;
    int tid = threadIdx.x, lane = tid & 31, warp = tid >> 5;

    __shared__ unsigned s_bits[P];          // 34928 B
    __shared__ int      s_hist[2048];       // 8192 B
    __shared__ int      s_gs[64];
    __shared__ float    s_fa[32], s_fb[32];
    __shared__ int      s_ia[32];
    __shared__ int      sh_k, sh_rem;
    __shared__ unsigned sh_pref;
    __shared__ float    sh_lcpos;

    // stage mine bits early (long-latency gmem loads in flight)
    #pragma unroll
    for (int j = 0; j < 9; j++) {
        int i = tid + j * 1024;
        if (i < P) s_bits[i] = __float_as_uint(g_mine[b * P + i]);
    }

    // reduce k_main partials (CPB=69 entries -> warps 0..2)
    float ll = 0.f, lc = 0.f; int np = 0;
    if (tid < CPB) {
        int idx = b * CPB + tid;
        ll = g_part_lossl[idx]; lc = g_part_lcpos[idx]; np = g_part_npos[idx];
    }
    #pragma unroll
    for (int s = 16; s > 0; s >>= 1) {
        ll += __shfl_xor_sync(0xffffffffu, ll, s);
        lc += __shfl_xor_sync(0xffffffffu, lc, s);
        np += __shfl_xor_sync(0xffffffffu, np, s);
    }
    if (lane == 0) { s_fa[warp] = ll; s_fb[warp] = lc; s_ia[warp] = np; }
    __syncthreads();
    if (tid == 0) {
        float tll = 0.f, tlc = 0.f; int tnp = 0;
        #pragma unroll
        for (int w = 0; w < 3; w++) { tll += s_fa[w]; tlc += s_fb[w]; tnp += s_ia[w]; }
        g_lossl_b[b] = tll;
        g_npos_b[b]  = tnp;
        sh_lcpos = tlc;
        int k = 3 * tnp; if (k > P - 1) k = P - 1;
        sh_k = k;
        sh_rem = k;
        sh_pref = 0u;
    }
    __syncthreads();

    int k = sh_k;
    if (k <= 0) {
        if (tid == 0) g_lossc_b[b] = sh_lcpos;
        return;
    }

    const int shifts[3]    = {21, 10, 0};
    const unsigned msks[3] = {0x00000000u, 0xFFE00000u, 0xFFFFFC00u};
    const int nbuck[3]     = {2048, 2048, 1024};

    for (int lev = 0; lev < 3; lev++) {
        int nb = nbuck[lev];
        for (int i = tid; i < nb; i += 1024) s_hist[i] = 0;
        __syncthreads();
        unsigned msk = msks[lev], pref = sh_pref;
        int sh = shifts[lev];
        unsigned bmask = (unsigned)(nb - 1);
        #pragma unroll
        for (int j = 0; j < 9; j++) {
            int i = tid + j * 1024;
            bool ok = false; unsigned bkt = 0;
            if (i < P) {
                unsigned x = s_bits[i];
                ok = ((x & msk) == pref);
                bkt = (x >> sh) & bmask;
            }
            unsigned active = __ballot_sync(0xffffffffu, ok);
            if (ok) {
                // warp-aggregate: one atomic per distinct bucket per warp
                unsigned peers = __match_any_sync(active, bkt);
                int leader = __ffs(peers) - 1;
                if (lane == leader) atomicAdd(&s_hist[bkt], __popc(peers));
            }
        }
        __syncthreads();
        int ng = nb >> 5;
        if (tid < ng) {
            int s = 0;
            #pragma unroll
            for (int j = 0; j < 32; j++) s += s_hist[tid * 32 + j];
            s_gs[tid] = s;
        }
        __syncthreads();

        if (tid < 32) {
            int rem = sh_rem;
            int g, remAfter;
            if (ng == 64) {
                int suf1 = warp_suffix(s_gs[32 + lane], lane);
                int tot1 = __shfl_sync(0xffffffffu, suf1, 0);
                int suf0 = warp_suffix(s_gs[lane], lane);
                unsigned m1 = __ballot_sync(0xffffffffu, suf1 >= rem);
                if (m1) {
                    int l = 31 - __clz(m1);
                    g = 32 + l;
                    remAfter = (l == 31) ? 0 : __shfl_sync(0xffffffffu, suf1, l + 1);
                } else {
                    unsigned m0 = __ballot_sync(0xffffffffu, (suf0 + tot1) >= rem);
                    int l = m0 ? (31 - __clz(m0)) : 0;
                    g = l;
                    remAfter = ((l == 31) ? 0 : __shfl_sync(0xffffffffu, suf0, l + 1)) + tot1;
                }
            } else {
                int suf = warp_suffix(s_gs[lane], lane);
                unsigned m = __ballot_sync(0xffffffffu, suf >= rem);
                int l = m ? (31 - __clz(m)) : 0;
                g = l;
                remAfter = (l == 31) ? 0 : __shfl_sync(0xffffffffu, suf, l + 1);
            }
            int rem2 = rem - remAfter;
            int sufh = warp_suffix(s_hist[g * 32 + lane], lane);
            unsigned mh = __ballot_sync(0xffffffffu, sufh >= rem2);
            int j = mh ? (31 - __clz(mh)) : 0;
            int after = (j == 31) ? 0 : __shfl_sync(0xffffffffu, sufh, j + 1);
            if (lane == 0) {
                sh_rem = rem2 - after;
                sh_pref = sh_pref | (((unsigned)(g * 32 + j)) << sh);
            }
        }
        __syncthreads();
    }

    unsigned vk = sh_pref;
    int cg = 0; float sg = 0.f;
    #pragma unroll
    for (int j = 0; j < 9; j++) {
        int i = tid + j * 1024;
        if (i < P) {
            unsigned x = s_bits[i];
            if (x > vk) { cg++; sg += __uint_as_float(x); }
        }
    }
    #pragma unroll
    for (int s = 16; s > 0; s >>= 1) {
        cg += __shfl_xor_sync(0xffffffffu, cg, s);
        sg += __shfl_xor_sync(0xffffffffu, sg, s);
    }
    if (lane == 0) { s_ia[warp] = cg; s_fa[warp] = sg; }
    __syncthreads();
    if (tid == 0) {
        int g = 0; float s = 0.f;
        #pragma unroll
        for (int w = 0; w < 32; w++) { g += s_ia[w]; s += s_fa[w]; }
        float lneg = s + (float)(k - g) * __uint_as_float(vk);
        g_lossc_b[b] = sh_lcpos + lneg;
    }
}

// ---------------- kernel 5: final combine (64-thread reduce) -----------------
__global__ void k_fin(float* __restrict__ out) {
    __shared__ float s_l[2], s_c[2];
    __shared__ int   s_n[2];
    int tid = threadIdx.x, lane = tid & 31, warp = tid >> 5;
    float ll = 0.f, lcc = 0.f; int n = 0;
    if (tid < B) { ll = g_lossl_b[tid]; lcc = g_lossc_b[tid]; n = g_npos_b[tid]; }
    #pragma unroll
    for (int s = 16; s > 0; s >>= 1) {
        ll  += __shfl_xor_sync(0xffffffffu, ll, s);
        lcc += __shfl_xor_sync(0xffffffffu, lcc, s);
        n   += __shfl_xor_sync(0xffffffffu, n, s);
    }
    if (lane == 0) { s_l[warp] = ll; s_c[warp] = lcc; s_n[warp] = n; }
    __syncthreads();
    if (tid == 0) {
        float fN = (float)(s_n[0] + s_n[1]);
        out[0] = (s_l[0] + s_l[1]) / fN + (s_c[0] + s_c[1]) / fN;
    }
}

// ---------------- launch ----------------
extern "C" void kernel_launch(void* const* d_in, const int* in_sizes, int n_in,
                              void* d_out, int out_size) {
    const float* loc     = (const float*)d_in[0];   // (B,P,4)
    const float* conf    = (const float*)d_in[1];   // (B,P,NC)
    const float* priors  = (const float*)d_in[2];   // (P,4)
    const float* targets = (const float*)d_in[3];   // (B,NOBJ,5)
    float* out = (float*)d_out;

    k_match<<<dim3(NBX, B), 256>>>(priors, targets);
    k_force<<<1, 64>>>();
    k_main<<<B * CPB, TPB>>>(loc, conf, priors, targets);
    k_negred<<<B, 1024>>>();
    k_fin<<<1, 64>>>(out);
}

// round 8
// speedup vs baseline: 1.1245x; 1.1245x over previous
#include <cuda_runtime.h>
#include <math.h>

#define B 64
#define P 8732
#define NOBJ 16
#define NC 81
#define THRESH 0.5f
#define RPB 128                 // conf rows per block in k_main
#define CPB 69                  // ceil(P/RPB)
#define NPART (B*CPB)

#define PPB 35                  // per-prior blocks per batch: ceil(8732/256)
#define TSL 8                   // truth-slice blocks per batch
#define SLICE 1092              // ceil(P/TSL)
#define NBX (PPB + TSL)

// ---------------- scratch (device globals; no allocs allowed) ----------------
__device__ float              g_overlap[B*P];
__device__ int                g_tidx[B*P];
__device__ float              g_mine[B*P];
__device__ unsigned long long g_bestprior[B*NOBJ];   // zero at load; k_force restores zeros

__device__ float g_part_lossl[NPART];
__device__ float g_part_lcpos[NPART];
__device__ int   g_part_npos[NPART];

__device__ float g_lossl_b[B];
__device__ float g_lossc_b[B];
__device__ int   g_npos_b[B];

__device__ __forceinline__ float smooth_l1(float x) {
    float ax = fabsf(x);
    return (ax < 1.0f) ? 0.5f * x * x : ax - 0.5f;
}

__device__ __forceinline__ int warp_suffix(int x, int lane) {
    #pragma unroll
    for (int s = 1; s < 32; s <<= 1) {
        int v = __shfl_down_sync(0xffffffffu, x, s);
        if (lane + s < 32) x += v;
    }
    return x;   // x[lane] = sum_{j>=lane} input[j]
}

// ---------------- kernel 1: matching (split design) ----------------
// grid (NBX, B), block 256.
//  bx < PPB  : per-prior best-truth argmax (thread per prior)
//  bx >= PPB : per-truth best-prior argmax (warp per 2 truths over a P-slice)
__global__ void k_match(const float* __restrict__ priors,
                        const float* __restrict__ targets) {
    int b  = blockIdx.y;
    int bx = blockIdx.x;
    int tid = threadIdx.x;
    int lane = tid & 31;
    int warp = tid >> 5;

    __shared__ float s_t[NOBJ * 5];
    if (tid < NOBJ * 5) s_t[tid] = targets[b * NOBJ * 5 + tid];
    __syncthreads();

    if (bx < PPB) {
        int p = bx * 256 + tid;
        if (p >= P) return;
        float4 pr = *(const float4*)(priors + p * 4);
        float px1 = pr.x - pr.z * 0.5f, py1 = pr.y - pr.w * 0.5f;
        float px2 = pr.x + pr.z * 0.5f, py2 = pr.y + pr.w * 0.5f;
        float pa  = (px2 - px1) * (py2 - py1);

        float bestv = -1.0f; int besti = 0;
        #pragma unroll
        for (int t = 0; t < NOBJ; t++) {
            float tx1 = s_t[t*5+0], ty1 = s_t[t*5+1], tx2 = s_t[t*5+2], ty2 = s_t[t*5+3];
            float ix1 = fmaxf(tx1, px1), iy1 = fmaxf(ty1, py1);
            float ix2 = fminf(tx2, px2), iy2 = fminf(ty2, py2);
            float iw = fmaxf(ix2 - ix1, 0.f), ih = fmaxf(iy2 - iy1, 0.f);
            float inter = iw * ih;
            float ta = (tx2 - tx1) * (ty2 - ty1);
            float iou = inter / (ta + pa - inter);
            if (iou > bestv) { bestv = iou; besti = t; }
        }
        g_overlap[b * P + p] = bestv;
        g_tidx[b * P + p]    = besti;
    } else {
        int ts = bx - PPB;
        int p_lo = ts * SLICE;
        int p_hi = min(P, p_lo + SLICE);

        #pragma unroll
        for (int r = 0; r < 2; r++) {
            int t = warp * 2 + r;
            float tx1 = s_t[t*5+0], ty1 = s_t[t*5+1], tx2 = s_t[t*5+2], ty2 = s_t[t*5+3];
            float ta = (tx2 - tx1) * (ty2 - ty1);

            unsigned long long key = 0ULL;
            for (int p = p_lo + lane; p < p_hi; p += 32) {
                float4 pr = *(const float4*)(priors + p * 4);
                float px1 = pr.x - pr.z * 0.5f, py1 = pr.y - pr.w * 0.5f;
                float px2 = pr.x + pr.z * 0.5f, py2 = pr.y + pr.w * 0.5f;
                float pa  = (px2 - px1) * (py2 - py1);
                float ix1 = fmaxf(tx1, px1), iy1 = fmaxf(ty1, py1);
                float ix2 = fminf(tx2, px2), iy2 = fminf(ty2, py2);
                float iw = fmaxf(ix2 - ix1, 0.f), ih = fmaxf(iy2 - iy1, 0.f);
                float inter = iw * ih;
                float iou = inter / (ta + pa - inter);
                unsigned long long k =
                    ((((unsigned long long)__float_as_uint(iou)) << 32) |
                     (unsigned long long)(0xFFFFFFFFu - (unsigned)p));
                if (k > key) key = k;
            }
            #pragma unroll
            for (int s = 16; s > 0; s >>= 1) {
                unsigned long long o = __shfl_xor_sync(0xffffffffu, key, s);
                if (o > key) key = o;
            }
            if (lane == 0) atomicMax(&g_bestprior[b * NOBJ + t], key);
        }
    }
}

// ---------------- kernel 2: force best-prior matches + reset keys ------------
__global__ void k_force() {
    int b = threadIdx.x;
    if (b < B) {
        for (int j = 0; j < NOBJ; j++) {
            unsigned long long key = g_bestprior[b * NOBJ + j];
            g_bestprior[b * NOBJ + j] = 0ULL;   // restore for next graph replay
            unsigned p = 0xFFFFFFFFu - (unsigned)(key & 0xFFFFFFFFull);
            g_overlap[b * P + p] = 2.0f;
            g_tidx[b * P + p]    = j;
        }
    }
}

// ---------------- kernel 3: main heavy kernel (EXACT 107us config) -----------
// thread per prior, scalar fully-unrolled smem staging, 128 threads/block
__global__ void __launch_bounds__(RPB) k_main(const float* __restrict__ loc,
                                              const float* __restrict__ conf,
                                              const float* __restrict__ priors,
                                              const float* __restrict__ targets) {
    int blk = blockIdx.x;
    int b   = blk / CPB;
    int c   = blk % CPB;
    int p0  = c * RPB;
    int nrows = (p0 + RPB <= P) ? RPB : (P - p0);

    __shared__ float s_conf[RPB * NC];      // 41472 B
    __shared__ float s_ll[4], s_lc[4];
    __shared__ int   s_np[4];

    const float* base = conf + ((size_t)b * P + p0) * NC;
    int tid = threadIdx.x;

    if (nrows == RPB) {
        #pragma unroll
        for (int j = 0; j < NC; j++)
            s_conf[tid + j * RPB] = __ldg(base + tid + j * RPB);
    } else {
        int total = nrows * NC;
        for (int i = tid; i < total; i += RPB)
            s_conf[i] = __ldg(base + i);
    }
    __syncthreads();

    float lossl = 0.f, lcpos = 0.f; int np = 0;

    if (tid < nrows) {
        int p = p0 + tid;
        const float* row = s_conf + tid * NC;

        float sum = 0.f;
        #pragma unroll
        for (int j = 0; j < NC; j++) sum += __expf(row[j]);
        float lse = __logf(sum);

        float ov = g_overlap[b * P + p];
        int   t  = g_tidx[b * P + p];
        bool  pos = (ov >= THRESH);
        int   ct = 0;
        if (pos) ct = (int)__ldg(&targets[(b * NOBJ + t) * 5 + 4]) + 1;

        float lc = lse - row[ct];
        g_mine[b * P + p] = pos ? 0.f : lc;

        if (pos) {
            np = 1; lcpos = lc;
            float4 pr = *(const float4*)(priors + p * 4);
            const float* tr = targets + (b * NOBJ + t) * 5;
            float mx1 = tr[0], my1 = tr[1], mx2 = tr[2], my2 = tr[3];
            float gcx = ((mx1 + mx2) * 0.5f - pr.x) / (0.1f * pr.z);
            float gcy = ((my1 + my2) * 0.5f - pr.y) / (0.1f * pr.w);
            float gw  = __logf((mx2 - mx1) / pr.z) * 5.0f;
            float gh  = __logf((my2 - my1) / pr.w) * 5.0f;
            float4 ld = *(const float4*)(loc + ((size_t)b * P + p) * 4);
            lossl = smooth_l1(ld.x - gcx) + smooth_l1(ld.y - gcy)
                  + smooth_l1(ld.z - gw)  + smooth_l1(ld.w - gh);
        }
    }

    int lane = tid & 31, warp = tid >> 5;
    #pragma unroll
    for (int s = 16; s > 0; s >>= 1) {
        lossl += __shfl_xor_sync(0xffffffffu, lossl, s);
        lcpos += __shfl_xor_sync(0xffffffffu, lcpos, s);
        np    += __shfl_xor_sync(0xffffffffu, np, s);
    }
    if (lane == 0) { s_ll[warp] = lossl; s_lc[warp] = lcpos; s_np[warp] = np; }
    __syncthreads();
    if (tid == 0) {
        float a = 0.f, bb = 0.f; int n = 0;
        #pragma unroll
        for (int w = 0; w < 4; w++) { a += s_ll[w]; bb += s_lc[w]; n += s_np[w]; }
        g_part_lossl[blk] = a;
        g_part_lcpos[blk] = bb;
        g_part_npos[blk]  = n;
    }
}

// ---------------- kernel 4: per-batch reduce + hard-negative mining ----------
// grid B, block 1024. 3-level histogram top-k, warp-parallel bucket selection,
// plain smem atomics (warp-aggregation measured slower).
__global__ void __launch_bounds__(1024) k_negred() {
    int b = blockIdx.x;
    int tid = threadIdx.x, lane = tid & 31, warp = tid >> 5;

    __shared__ unsigned s_bits[P];          // 34928 B
    __shared__ int      s_hist[2048];       // 8192 B
    __shared__ int      s_gs[64];
    __shared__ float    s_fa[32], s_fb[32];
    __shared__ int      s_ia[32];
    __shared__ int      sh_k, sh_rem;
    __shared__ unsigned sh_pref;
    __shared__ float    sh_lcpos;

    // stage mine bits early (long-latency gmem loads in flight)
    #pragma unroll
    for (int j = 0; j < 9; j++) {
        int i = tid + j * 1024;
        if (i < P) s_bits[i] = __float_as_uint(g_mine[b * P + i]);
    }

    // reduce k_main partials (CPB=69 entries -> warps 0..2)
    float ll = 0.f, lc = 0.f; int np = 0;
    if (tid < CPB) {
        int idx = b * CPB + tid;
        ll = g_part_lossl[idx]; lc = g_part_lcpos[idx]; np = g_part_npos[idx];
    }
    #pragma unroll
    for (int s = 16; s > 0; s >>= 1) {
        ll += __shfl_xor_sync(0xffffffffu, ll, s);
        lc += __shfl_xor_sync(0xffffffffu, lc, s);
        np += __shfl_xor_sync(0xffffffffu, np, s);
    }
    if (lane == 0) { s_fa[warp] = ll; s_fb[warp] = lc; s_ia[warp] = np; }
    __syncthreads();
    if (tid == 0) {
        float tll = 0.f, tlc = 0.f; int tnp = 0;
        #pragma unroll
        for (int w = 0; w < 3; w++) { tll += s_fa[w]; tlc += s_fb[w]; tnp += s_ia[w]; }
        g_lossl_b[b] = tll;
        g_npos_b[b]  = tnp;
        sh_lcpos = tlc;
        int k = 3 * tnp; if (k > P - 1) k = P - 1;
        sh_k = k;
        sh_rem = k;
        sh_pref = 0u;
    }
    __syncthreads();

    int k = sh_k;
    if (k <= 0) {
        if (tid == 0) g_lossc_b[b] = sh_lcpos;
        return;
    }

    const int shifts[3]    = {21, 10, 0};
    const unsigned msks[3] = {0x00000000u, 0xFFE00000u, 0xFFFFFC00u};
    const int nbuck[3]     = {2048, 2048, 1024};

    for (int lev = 0; lev < 3; lev++) {
        int nb = nbuck[lev];
        for (int i = tid; i < nb; i += 1024) s_hist[i] = 0;
        __syncthreads();
        unsigned msk = msks[lev], pref = sh_pref;
        int sh = shifts[lev];
        unsigned bmask = (unsigned)(nb - 1);
        #pragma unroll
        for (int j = 0; j < 9; j++) {
            int i = tid + j * 1024;
            if (i < P) {
                unsigned x = s_bits[i];
                if ((x & msk) == pref)
                    atomicAdd(&s_hist[(x >> sh) & bmask], 1);
            }
        }
        __syncthreads();
        int ng = nb >> 5;
        if (tid < ng) {
            int s = 0;
            #pragma unroll
            for (int j = 0; j < 32; j++) s += s_hist[tid * 32 + j];
            s_gs[tid] = s;
        }
        __syncthreads();

        // warp-parallel selection (warp 0 only) — measured good in R3
        if (tid < 32) {
            int rem = sh_rem;
            int g, remAfter;
            if (ng == 64) {
                int suf1 = warp_suffix(s_gs[32 + lane], lane);
                int tot1 = __shfl_sync(0xffffffffu, suf1, 0);
                int suf0 = warp_suffix(s_gs[lane], lane);
                unsigned m1 = __ballot_sync(0xffffffffu, suf1 >= rem);
                if (m1) {
                    int l = 31 - __clz(m1);
                    g = 32 + l;
                    remAfter = (l == 31) ? 0 : __shfl_sync(0xffffffffu, suf1, l + 1);
                } else {
                    unsigned m0 = __ballot_sync(0xffffffffu, (suf0 + tot1) >= rem);
                    int l = m0 ? (31 - __clz(m0)) : 0;
                    g = l;
                    remAfter = ((l == 31) ? 0 : __shfl_sync(0xffffffffu, suf0, l + 1)) + tot1;
                }
            } else {
                int suf = warp_suffix(s_gs[lane], lane);
                unsigned m = __ballot_sync(0xffffffffu, suf >= rem);
                int l = m ? (31 - __clz(m)) : 0;
                g = l;
                remAfter = (l == 31) ? 0 : __shfl_sync(0xffffffffu, suf, l + 1);
            }
            int rem2 = rem - remAfter;
            int sufh = warp_suffix(s_hist[g * 32 + lane], lane);
            unsigned mh = __ballot_sync(0xffffffffu, sufh >= rem2);
            int j = mh ? (31 - __clz(mh)) : 0;
            int after = (j == 31) ? 0 : __shfl_sync(0xffffffffu, sufh, j + 1);
            if (lane == 0) {
                sh_rem = rem2 - after;
                sh_pref = sh_pref | (((unsigned)(g * 32 + j)) << sh);
            }
        }
        __syncthreads();
    }

    unsigned vk = sh_pref;
    int cg = 0; float sg = 0.f;
    #pragma unroll
    for (int j = 0; j < 9; j++) {
        int i = tid + j * 1024;
        if (i < P) {
            unsigned x = s_bits[i];
            if (x > vk) { cg++; sg += __uint_as_float(x); }
        }
    }
    #pragma unroll
    for (int s = 16; s > 0; s >>= 1) {
        cg += __shfl_xor_sync(0xffffffffu, cg, s);
        sg += __shfl_xor_sync(0xffffffffu, sg, s);
    }
    if (lane == 0) { s_ia[warp] = cg; s_fa[warp] = sg; }
    __syncthreads();
    if (tid == 0) {
        int g = 0; float s = 0.f;
        #pragma unroll
        for (int w = 0; w < 32; w++) { g += s_ia[w]; s += s_fa[w]; }
        float lneg = s + (float)(k - g) * __uint_as_float(vk);
        g_lossc_b[b] = sh_lcpos + lneg;
    }
}

// ---------------- kernel 5: final combine (64-thread reduce) -----------------
__global__ void k_fin(float* __restrict__ out) {
    __shared__ float s_l[2], s_c[2];
    __shared__ int   s_n[2];
    int tid = threadIdx.x, lane = tid & 31, warp = tid >> 5;
    float ll = 0.f, lcc = 0.f; int n = 0;
    if (tid < B) { ll = g_lossl_b[tid]; lcc = g_lossc_b[tid]; n = g_npos_b[tid]; }
    #pragma unroll
    for (int s = 16; s > 0; s >>= 1) {
        ll  += __shfl_xor_sync(0xffffffffu, ll, s);
        lcc += __shfl_xor_sync(0xffffffffu, lcc, s);
        n   += __shfl_xor_sync(0xffffffffu, n, s);
    }
    if (lane == 0) { s_l[warp] = ll; s_c[warp] = lcc; s_n[warp] = n; }
    __syncthreads();
    if (tid == 0) {
        float fN = (float)(s_n[0] + s_n[1]);
        out[0] = (s_l[0] + s_l[1]) / fN + (s_c[0] + s_c[1]) / fN;
    }
}

// ---------------- launch ----------------
extern "C" void kernel_launch(void* const* d_in, const int* in_sizes, int n_in,
                              void* d_out, int out_size) {
    const float* loc     = (const float*)d_in[0];   // (B,P,4)
    const float* conf    = (const float*)d_in[1];   // (B,P,NC)
    const float* priors  = (const float*)d_in[2];   // (P,4)
    const float* targets = (const float*)d_in[3];   // (B,NOBJ,5)
    float* out = (float*)d_out;

    k_match<<<dim3(NBX, B), 256>>>(priors, targets);
    k_force<<<1, 64>>>();
    k_main<<<B * CPB, RPB>>>(loc, conf, priors, targets);
    k_negred<<<B, 1024>>>();
    k_fin<<<1, 64>>>(out);
}

// round 9
// speedup vs baseline: 1.3575x; 1.2073x over previous
#include <cuda_runtime.h>
#include <math.h>

#define B 64
#define P 8732
#define NOBJ 16
#define NC 81
#define THRESH 0.5f
#define RPB 128                 // conf rows per block in k_main
#define CPB 69                  // ceil(P/RPB)
#define NPART (B*CPB)
#define MBX 35                  // ceil(P/256) blocks per batch in k_match
#define NBLK_MATCH (MBX*B)

// ---------------- scratch (device globals; no allocs allowed) ----------------
__device__ float              g_overlap[B*P];
__device__ int                g_tidx[B*P];
__device__ float              g_mine[B*P];
__device__ unsigned long long g_bestprior[B*NOBJ];   // zero at load; force restores zeros

__device__ float g_part_lossl[NPART];
__device__ float g_part_lcpos[NPART];
__device__ int   g_part_npos[NPART];

__device__ float g_lossl_b[B];
__device__ float g_lossc_b[B];
__device__ int   g_npos_b[B];

__device__ int g_ctr_match;     // zero at load; last block resets
__device__ int g_ctr_neg;      // zero at load; last block resets

__device__ __forceinline__ float smooth_l1(float x) {
    float ax = fabsf(x);
    return (ax < 1.0f) ? 0.5f * x * x : ax - 0.5f;
}

__device__ __forceinline__ int warp_suffix(int x, int lane) {
    #pragma unroll
    for (int s = 1; s < 32; s <<= 1) {
        int v = __shfl_down_sync(0xffffffffu, x, s);
        if (lane + s < 32) x += v;
    }
    return x;   // x[lane] = sum_{j>=lane} input[j]
}

// ---------------- kernel 1: matching (combined, 107us design) + fused force --
// grid (MBX, B), block 256
__global__ void k_match(const float* __restrict__ priors,
                        const float* __restrict__ targets) {
    int b = blockIdx.y;
    int p = blockIdx.x * 256 + threadIdx.x;
    int tid = threadIdx.x;
    int lane = tid & 31;
    int warp = tid >> 5;

    __shared__ float s_t[NOBJ * 5];
    __shared__ unsigned long long s_wkey[8][NOBJ];
    __shared__ bool s_last;

    if (tid < NOBJ * 5) s_t[tid] = targets[b * NOBJ * 5 + tid];
    if (tid == 0) s_last = false;
    __syncthreads();

    bool valid = (p < P);
    float px1 = 0.f, py1 = 0.f, px2 = 0.f, py2 = 0.f, pa = 0.f;
    if (valid) {
        float4 pr = *(const float4*)(priors + p * 4);
        px1 = pr.x - pr.z * 0.5f; py1 = pr.y - pr.w * 0.5f;
        px2 = pr.x + pr.z * 0.5f; py2 = pr.y + pr.w * 0.5f;
        pa  = (px2 - px1) * (py2 - py1);
    }

    float bestv = -1.0f; int besti = 0;
    #pragma unroll
    for (int t = 0; t < NOBJ; t++) {
        float tx1 = s_t[t*5+0], ty1 = s_t[t*5+1], tx2 = s_t[t*5+2], ty2 = s_t[t*5+3];
        float ix1 = fmaxf(tx1, px1), iy1 = fmaxf(ty1, py1);
        float ix2 = fminf(tx2, px2), iy2 = fminf(ty2, py2);
        float iw = fmaxf(ix2 - ix1, 0.f), ih = fmaxf(iy2 - iy1, 0.f);
        float inter = iw * ih;
        float ta = (tx2 - tx1) * (ty2 - ty1);
        float iou = inter / (ta + pa - inter);
        if (valid && iou > bestv) { bestv = iou; besti = t; }
        // packed key: high=float bits (iou>=0), low = ~p so ties pick smallest p
        unsigned long long key = valid
            ? ((((unsigned long long)__float_as_uint(iou)) << 32) |
               (unsigned long long)(0xFFFFFFFFu - (unsigned)p))
            : 0ULL;
        #pragma unroll
        for (int s = 16; s > 0; s >>= 1) {
            unsigned long long o = __shfl_xor_sync(0xffffffffu, key, s);
            if (o > key) key = o;
        }
        if (lane == 0) s_wkey[warp][t] = key;
    }

    if (valid) {
        g_overlap[b * P + p] = bestv;
        g_tidx[b * P + p]    = besti;
    }
    __syncthreads();

    if (tid < NOBJ) {
        unsigned long long k = 0ULL;
        #pragma unroll
        for (int w = 0; w < 8; w++) {
            unsigned long long v = s_wkey[w][tid];
            if (v > k) k = v;
        }
        atomicMax(&g_bestprior[b * NOBJ + tid], k);
    }
    __syncthreads();

    // ---- fused force step: last arriving block does it for all batches ----
    if (tid == 0) {
        __threadfence();                       // publish writes + atomics
        int old = atomicAdd(&g_ctr_match, 1);
        s_last = (old == NBLK_MATCH - 1);
    }
    __syncthreads();
    if (s_last) {
        __threadfence();                       // acquire others' writes
        if (tid < B) {
            int bb = tid;
            for (int j = 0; j < NOBJ; j++) {   // j ascending: scatter order
                unsigned long long key = g_bestprior[bb * NOBJ + j];
                g_bestprior[bb * NOBJ + j] = 0ULL;   // restore for next replay
                unsigned pp = 0xFFFFFFFFu - (unsigned)(key & 0xFFFFFFFFull);
                g_overlap[bb * P + pp] = 2.0f;
                g_tidx[bb * P + pp]    = j;
            }
        }
        if (tid == 0) g_ctr_match = 0;         // reset for next replay
    }
}

// ---------------- kernel 2: main heavy kernel (EXACT 107us config) -----------
// thread per prior, scalar fully-unrolled smem staging, 128 threads/block
__global__ void __launch_bounds__(RPB) k_main(const float* __restrict__ loc,
                                              const float* __restrict__ conf,
                                              const float* __restrict__ priors,
                                              const float* __restrict__ targets) {
    int blk = blockIdx.x;
    int b   = blk / CPB;
    int c   = blk % CPB;
    int p0  = c * RPB;
    int nrows = (p0 + RPB <= P) ? RPB : (P - p0);

    __shared__ float s_conf[RPB * NC];      // 41472 B
    __shared__ float s_ll[4], s_lc[4];
    __shared__ int   s_np[4];

    const float* base = conf + ((size_t)b * P + p0) * NC;
    int tid = threadIdx.x;

    if (nrows == RPB) {
        #pragma unroll
        for (int j = 0; j < NC; j++)
            s_conf[tid + j * RPB] = __ldg(base + tid + j * RPB);
    } else {
        int total = nrows * NC;
        for (int i = tid; i < total; i += RPB)
            s_conf[i] = __ldg(base + i);
    }
    __syncthreads();

    float lossl = 0.f, lcpos = 0.f; int np = 0;

    if (tid < nrows) {
        int p = p0 + tid;
        const float* row = s_conf + tid * NC;

        float sum = 0.f;
        #pragma unroll
        for (int j = 0; j < NC; j++) sum += __expf(row[j]);
        float lse = __logf(sum);

        float ov = g_overlap[b * P + p];
        int   t  = g_tidx[b * P + p];
        bool  pos = (ov >= THRESH);
        int   ct = 0;
        if (pos) ct = (int)__ldg(&targets[(b * NOBJ + t) * 5 + 4]) + 1;

        float lc = lse - row[ct];
        g_mine[b * P + p] = pos ? 0.f : lc;

        if (pos) {
            np = 1; lcpos = lc;
            float4 pr = *(const float4*)(priors + p * 4);
            const float* tr = targets + (b * NOBJ + t) * 5;
            float mx1 = tr[0], my1 = tr[1], mx2 = tr[2], my2 = tr[3];
            float gcx = ((mx1 + mx2) * 0.5f - pr.x) / (0.1f * pr.z);
            float gcy = ((my1 + my2) * 0.5f - pr.y) / (0.1f * pr.w);
            float gw  = __logf((mx2 - mx1) / pr.z) * 5.0f;
            float gh  = __logf((my2 - my1) / pr.w) * 5.0f;
            float4 ld = *(const float4*)(loc + ((size_t)b * P + p) * 4);
            lossl = smooth_l1(ld.x - gcx) + smooth_l1(ld.y - gcy)
                  + smooth_l1(ld.z - gw)  + smooth_l1(ld.w - gh);
        }
    }

    int lane = tid & 31, warp = tid >> 5;
    #pragma unroll
    for (int s = 16; s > 0; s >>= 1) {
        lossl += __shfl_xor_sync(0xffffffffu, lossl, s);
        lcpos += __shfl_xor_sync(0xffffffffu, lcpos, s);
        np    += __shfl_xor_sync(0xffffffffu, np, s);
    }
    if (lane == 0) { s_ll[warp] = lossl; s_lc[warp] = lcpos; s_np[warp] = np; }
    __syncthreads();
    if (tid == 0) {
        float a = 0.f, bb = 0.f; int n = 0;
        #pragma unroll
        for (int w = 0; w < 4; w++) { a += s_ll[w]; bb += s_lc[w]; n += s_np[w]; }
        g_part_lossl[blk] = a;
        g_part_lcpos[blk] = bb;
        g_part_npos[blk]  = n;
    }
}

// ---------------- kernel 3: per-batch reduce + negative mining + fused final -
// grid B, block 1024.
__global__ void __launch_bounds__(1024) k_negred(float* __restrict__ out) {
    int b = blockIdx.x;
    int tid = threadIdx.x, lane = tid & 31, warp = tid >> 5;

    __shared__ unsigned s_bits[P];          // 34928 B
    __shared__ int      s_hist[2048];       // 8192 B
    __shared__ int      s_gs[64];
    __shared__ float    s_fa[32], s_fb[32];
    __shared__ int      s_ia[32];
    __shared__ int      sh_k, sh_rem;
    __shared__ unsigned sh_pref;
    __shared__ float    sh_lcpos;
    __shared__ bool     s_last;

    // stage mine bits early (long-latency gmem loads in flight)
    #pragma unroll
    for (int j = 0; j < 9; j++) {
        int i = tid + j * 1024;
        if (i < P) s_bits[i] = __float_as_uint(g_mine[b * P + i]);
    }

    // reduce k_main partials (CPB=69 entries -> warps 0..2)
    float ll = 0.f, lc = 0.f; int np = 0;
    if (tid < CPB) {
        int idx = b * CPB + tid;
        ll = g_part_lossl[idx]; lc = g_part_lcpos[idx]; np = g_part_npos[idx];
    }
    #pragma unroll
    for (int s = 16; s > 0; s >>= 1) {
        ll += __shfl_xor_sync(0xffffffffu, ll, s);
        lc += __shfl_xor_sync(0xffffffffu, lc, s);
        np += __shfl_xor_sync(0xffffffffu, np, s);
    }
    if (lane == 0) { s_fa[warp] = ll; s_fb[warp] = lc; s_ia[warp] = np; }
    __syncthreads();
    if (tid == 0) {
        s_last = false;
        float tll = 0.f, tlc = 0.f; int tnp = 0;
        #pragma unroll
        for (int w = 0; w < 3; w++) { tll += s_fa[w]; tlc += s_fb[w]; tnp += s_ia[w]; }
        g_lossl_b[b] = tll;
        g_npos_b[b]  = tnp;
        sh_lcpos = tlc;
        int k = 3 * tnp; if (k > P - 1) k = P - 1;
        sh_k = k;
        sh_rem = k;
        sh_pref = 0u;
    }
    __syncthreads();

    int k = sh_k;
    if (k > 0) {
        const int shifts[3]    = {21, 10, 0};
        const unsigned msks[3] = {0x00000000u, 0xFFE00000u, 0xFFFFFC00u};
        const int nbuck[3]     = {2048, 2048, 1024};

        for (int lev = 0; lev < 3; lev++) {
            int nb = nbuck[lev];
            for (int i = tid; i < nb; i += 1024) s_hist[i] = 0;
            __syncthreads();
            unsigned msk = msks[lev], pref = sh_pref;
            int sh = shifts[lev];
            unsigned bmask = (unsigned)(nb - 1);
            #pragma unroll
            for (int j = 0; j < 9; j++) {
                int i = tid + j * 1024;
                if (i < P) {
                    unsigned x = s_bits[i];
                    if ((x & msk) == pref)
                        atomicAdd(&s_hist[(x >> sh) & bmask], 1);
                }
            }
            __syncthreads();
            int ng = nb >> 5;
            if (tid < ng) {
                int s = 0;
                #pragma unroll
                for (int j = 0; j < 32; j++) s += s_hist[tid * 32 + j];
                s_gs[tid] = s;
            }
            __syncthreads();

            // warp-parallel selection (warp 0 only)
            if (tid < 32) {
                int rem = sh_rem;
                int g, remAfter;
                if (ng == 64) {
                    int suf1 = warp_suffix(s_gs[32 + lane], lane);
                    int tot1 = __shfl_sync(0xffffffffu, suf1, 0);
                    int suf0 = warp_suffix(s_gs[lane], lane);
                    unsigned m1 = __ballot_sync(0xffffffffu, suf1 >= rem);
                    if (m1) {
                        int l = 31 - __clz(m1);
                        g = 32 + l;
                        remAfter = (l == 31) ? 0 : __shfl_sync(0xffffffffu, suf1, l + 1);
                    } else {
                        unsigned m0 = __ballot_sync(0xffffffffu, (suf0 + tot1) >= rem);
                        int l = m0 ? (31 - __clz(m0)) : 0;
                        g = l;
                        remAfter = ((l == 31) ? 0 : __shfl_sync(0xffffffffu, suf0, l + 1)) + tot1;
                    }
                } else {
                    int suf = warp_suffix(s_gs[lane], lane);
                    unsigned m = __ballot_sync(0xffffffffu, suf >= rem);
                    int l = m ? (31 - __clz(m)) : 0;
                    g = l;
                    remAfter = (l == 31) ? 0 : __shfl_sync(0xffffffffu, suf, l + 1);
                }
                int rem2 = rem - remAfter;
                int sufh = warp_suffix(s_hist[g * 32 + lane], lane);
                unsigned mh = __ballot_sync(0xffffffffu, sufh >= rem2);
                int j = mh ? (31 - __clz(mh)) : 0;
                int after = (j == 31) ? 0 : __shfl_sync(0xffffffffu, sufh, j + 1);
                if (lane == 0) {
                    sh_rem = rem2 - after;
                    sh_pref = sh_pref | (((unsigned)(g * 32 + j)) << sh);
                }
            }
            __syncthreads();
        }

        unsigned vk = sh_pref;
        int cg = 0; float sg = 0.f;
        #pragma unroll
        for (int j = 0; j < 9; j++) {
            int i = tid + j * 1024;
            if (i < P) {
                unsigned x = s_bits[i];
                if (x > vk) { cg++; sg += __uint_as_float(x); }
            }
        }
        #pragma unroll
        for (int s = 16; s > 0; s >>= 1) {
            cg += __shfl_xor_sync(0xffffffffu, cg, s);
            sg += __shfl_xor_sync(0xffffffffu, sg, s);
        }
        if (lane == 0) { s_ia[warp] = cg; s_fa[warp] = sg; }
        __syncthreads();
        if (tid == 0) {
            int g = 0; float s = 0.f;
            #pragma unroll
            for (int w = 0; w < 32; w++) { g += s_ia[w]; s += s_fa[w]; }
            float lneg = s + (float)(k - g) * __uint_as_float(vk);
            g_lossc_b[b] = sh_lcpos + lneg;
        }
    } else {
        if (tid == 0) g_lossc_b[b] = sh_lcpos;
    }

    // ---- fused final combine: last arriving block reduces all batches ----
    if (tid == 0) {
        __threadfence();                       // publish g_loss*_b, g_npos_b
        int old = atomicAdd(&g_ctr_neg, 1);
        s_last = (old == B - 1);
    }
    __syncthreads();
    if (s_last) {
        __threadfence();                       // acquire others' writes
        float fl = 0.f, fc = 0.f; int fn = 0;
        if (tid < B) { fl = g_lossl_b[tid]; fc = g_lossc_b[tid]; fn = g_npos_b[tid]; }
        #pragma unroll
        for (int s = 16; s > 0; s >>= 1) {
            fl += __shfl_xor_sync(0xffffffffu, fl, s);
            fc += __shfl_xor_sync(0xffffffffu, fc, s);
            fn += __shfl_xor_sync(0xffffffffu, fn, s);
        }
        if (lane == 0 && warp < 2) { s_fa[warp] = fl; s_fb[warp] = fc; s_ia[warp] = fn; }
        __syncthreads();
        if (tid == 0) {
            float fN = (float)(s_ia[0] + s_ia[1]);
            out[0] = (s_fa[0] + s_fa[1]) / fN + (s_fb[0] + s_fb[1]) / fN;
            g_ctr_neg = 0;                     // reset for next replay
        }
    }
}

// ---------------- launch ----------------
extern "C" void kernel_launch(void* const* d_in, const int* in_sizes, int n_in,
                              void* d_out, int out_size) {
    const float* loc     = (const float*)d_in[0];   // (B,P,4)
    const float* conf    = (const float*)d_in[1];   // (B,P,NC)
    const float* priors  = (const float*)d_in[2];   // (P,4)
    const float* targets = (const float*)d_in[3];   // (B,NOBJ,5)
    float* out = (float*)d_out;

    k_match<<<dim3(MBX, B), 256>>>(priors, targets);
    k_main<<<B * CPB, RPB>>>(loc, conf, priors, targets);
    k_negred<<<B, 1024>>>(out);
}

// round 10
// speedup vs baseline: 1.4435x; 1.0634x over previous
#include <cuda_runtime.h>
#include <math.h>

#define B 64
#define P 8732
#define NOBJ 16
#define NC 81
#define THRESH 0.5f
#define RPB 128                 // conf rows per block in k_main
#define CPB 69                  // ceil(P/RPB)
#define NPART (B*CPB)
#define MBX 35                  // ceil(P/256) blocks per batch in k_match
#define NBLK_MATCH (MBX*B)

// ---------------- scratch (device globals; no allocs allowed) ----------------
__device__ float              g_overlap[B*P];
__device__ int                g_tidx[B*P];
__device__ float              g_mine[B*P];
__device__ unsigned long long g_bestprior[B*NOBJ];   // zero at load; force restores zeros

__device__ float g_part_lossl[NPART];
__device__ float g_part_lcpos[NPART];
__device__ int   g_part_npos[NPART];

__device__ float g_lossl_b[B];
__device__ float g_lossc_b[B];
__device__ int   g_npos_b[B];

__device__ int g_ctr_match;     // zero at load; last block resets
__device__ int g_ctr_neg;       // zero at load; last block resets

__device__ __forceinline__ float smooth_l1(float x) {
    float ax = fabsf(x);
    return (ax < 1.0f) ? 0.5f * x * x : ax - 0.5f;
}

__device__ __forceinline__ int warp_suffix(int x, int lane) {
    #pragma unroll
    for (int s = 1; s < 32; s <<= 1) {
        int v = __shfl_down_sync(0xffffffffu, x, s);
        if (lane + s < 32) x += v;
    }
    return x;   // x[lane] = sum_{j>=lane} input[j]
}

// ---------------- kernel 1: matching + fused force ---------------------------
// grid (MBX, B), block 256. REDUX-based per-truth reduction.
__global__ void k_match(const float* __restrict__ priors,
                        const float* __restrict__ targets) {
    int b = blockIdx.y;
    int p = blockIdx.x * 256 + threadIdx.x;
    int tid = threadIdx.x;
    int lane = tid & 31;
    int warp = tid >> 5;
    int pbase = blockIdx.x * 256 + warp * 32;   // p of lane 0 in this warp

    __shared__ float s_t[NOBJ * 5];
    __shared__ unsigned long long s_wkey[8][NOBJ];
    __shared__ bool s_last;

    if (tid < NOBJ * 5) s_t[tid] = targets[b * NOBJ * 5 + tid];
    if (tid == 0) s_last = false;
    __syncthreads();

    bool valid = (p < P);
    float px1 = 0.f, py1 = 0.f, px2 = 0.f, py2 = 0.f, pa = 0.f;
    if (valid) {
        float4 pr = *(const float4*)(priors + p * 4);
        px1 = pr.x - pr.z * 0.5f; py1 = pr.y - pr.w * 0.5f;
        px2 = pr.x + pr.z * 0.5f; py2 = pr.y + pr.w * 0.5f;
        pa  = (px2 - px1) * (py2 - py1);
    }

    float bestv = -1.0f; int besti = 0;
    #pragma unroll
    for (int t = 0; t < NOBJ; t++) {
        float tx1 = s_t[t*5+0], ty1 = s_t[t*5+1], tx2 = s_t[t*5+2], ty2 = s_t[t*5+3];
        float ix1 = fmaxf(tx1, px1), iy1 = fmaxf(ty1, py1);
        float ix2 = fminf(tx2, px2), iy2 = fminf(ty2, py2);
        float iw = fmaxf(ix2 - ix1, 0.f), ih = fmaxf(iy2 - iy1, 0.f);
        float inter = iw * ih;
        float ta = (tx2 - tx1) * (ty2 - ty1);
        float iou = inter / (ta + pa - inter);
        if (valid && iou > bestv) { bestv = iou; besti = t; }

        // per-truth warp max: iou >= 0 so uint order == float order
        unsigned bits = valid ? __float_as_uint(iou) : 0u;
        unsigned wmax = __reduce_max_sync(0xffffffffu, bits);
        unsigned mask = __ballot_sync(0xffffffffu, valid && (bits == wmax));
        if (lane == 0) {
            unsigned long long key = 0ULL;
            if (mask) {
                int src = __ffs(mask) - 1;           // lowest lane = smallest p
                unsigned wp = (unsigned)(pbase + src);
                key = (((unsigned long long)wmax) << 32) |
                      (unsigned long long)(0xFFFFFFFFu - wp);
            }
            s_wkey[warp][t] = key;
        }
    }

    if (valid) {
        g_overlap[b * P + p] = bestv;
        g_tidx[b * P + p]    = besti;
    }
    __syncthreads();

    if (tid < NOBJ) {
        unsigned long long k = 0ULL;
        #pragma unroll
        for (int w = 0; w < 8; w++) {
            unsigned long long v = s_wkey[w][tid];
            if (v > k) k = v;
        }
        atomicMax(&g_bestprior[b * NOBJ + tid], k);
    }
    __syncthreads();

    // ---- fused force step: last arriving block does it for all batches ----
    if (tid == 0) {
        __threadfence();                       // publish writes + atomics
        int old = atomicAdd(&g_ctr_match, 1);
        s_last = (old == NBLK_MATCH - 1);
    }
    __syncthreads();
    if (s_last) {
        __threadfence();                       // acquire others' writes
        if (tid < B) {
            int bb = tid;
            for (int j = 0; j < NOBJ; j++) {   // j ascending: scatter order
                unsigned long long key = g_bestprior[bb * NOBJ + j];
                g_bestprior[bb * NOBJ + j] = 0ULL;   // restore for next replay
                unsigned pp = 0xFFFFFFFFu - (unsigned)(key & 0xFFFFFFFFull);
                g_overlap[bb * P + pp] = 2.0f;
                g_tidx[bb * P + pp]    = j;
            }
        }
        if (tid == 0) g_ctr_match = 0;         // reset for next replay
    }
}

// ---------------- kernel 2: main heavy kernel (EXACT 98.8us config) ----------
// thread per prior, scalar fully-unrolled smem staging, 128 threads/block
__global__ void __launch_bounds__(RPB) k_main(const float* __restrict__ loc,
                                              const float* __restrict__ conf,
                                              const float* __restrict__ priors,
                                              const float* __restrict__ targets) {
    int blk = blockIdx.x;
    int b   = blk / CPB;
    int c   = blk % CPB;
    int p0  = c * RPB;
    int nrows = (p0 + RPB <= P) ? RPB : (P - p0);

    __shared__ float s_conf[RPB * NC];      // 41472 B
    __shared__ float s_ll[4], s_lc[4];
    __shared__ int   s_np[4];

    const float* base = conf + ((size_t)b * P + p0) * NC;
    int tid = threadIdx.x;

    if (nrows == RPB) {
        #pragma unroll
        for (int j = 0; j < NC; j++)
            s_conf[tid + j * RPB] = __ldg(base + tid + j * RPB);
    } else {
        int total = nrows * NC;
        for (int i = tid; i < total; i += RPB)
            s_conf[i] = __ldg(base + i);
    }
    __syncthreads();

    float lossl = 0.f, lcpos = 0.f; int np = 0;

    if (tid < nrows) {
        int p = p0 + tid;
        const float* row = s_conf + tid * NC;

        float sum = 0.f;
        #pragma unroll
        for (int j = 0; j < NC; j++) sum += __expf(row[j]);
        float lse = __logf(sum);

        float ov = g_overlap[b * P + p];
        int   t  = g_tidx[b * P + p];
        bool  pos = (ov >= THRESH);
        int   ct = 0;
        if (pos) ct = (int)__ldg(&targets[(b * NOBJ + t) * 5 + 4]) + 1;

        float lc = lse - row[ct];
        g_mine[b * P + p] = pos ? 0.f : lc;

        if (pos) {
            np = 1; lcpos = lc;
            float4 pr = *(const float4*)(priors + p * 4);
            const float* tr = targets + (b * NOBJ + t) * 5;
            float mx1 = tr[0], my1 = tr[1], mx2 = tr[2], my2 = tr[3];
            float gcx = ((mx1 + mx2) * 0.5f - pr.x) / (0.1f * pr.z);
            float gcy = ((my1 + my2) * 0.5f - pr.y) / (0.1f * pr.w);
            float gw  = __logf((mx2 - mx1) / pr.z) * 5.0f;
            float gh  = __logf((my2 - my1) / pr.w) * 5.0f;
            float4 ld = *(const float4*)(loc + ((size_t)b * P + p) * 4);
            lossl = smooth_l1(ld.x - gcx) + smooth_l1(ld.y - gcy)
                  + smooth_l1(ld.z - gw)  + smooth_l1(ld.w - gh);
        }
    }

    int lane = tid & 31, warp = tid >> 5;
    #pragma unroll
    for (int s = 16; s > 0; s >>= 1) {
        lossl += __shfl_xor_sync(0xffffffffu, lossl, s);
        lcpos += __shfl_xor_sync(0xffffffffu, lcpos, s);
        np    += __shfl_xor_sync(0xffffffffu, np, s);
    }
    if (lane == 0) { s_ll[warp] = lossl; s_lc[warp] = lcpos; s_np[warp] = np; }
    __syncthreads();
    if (tid == 0) {
        float a = 0.f, bb = 0.f; int n = 0;
        #pragma unroll
        for (int w = 0; w < 4; w++) { a += s_ll[w]; bb += s_lc[w]; n += s_np[w]; }
        g_part_lossl[blk] = a;
        g_part_lcpos[blk] = bb;
        g_part_npos[blk]  = n;
    }
}

// ---------------- kernel 3: per-batch reduce + negative mining + fused final -
// grid B, block 1024.
__global__ void __launch_bounds__(1024) k_negred(float* __restrict__ out) {
    int b = blockIdx.x;
    int tid = threadIdx.x, lane = tid & 31, warp = tid >> 5;

    __shared__ unsigned s_bits[P];          // 34928 B
    __shared__ int      s_hist[2048];       // 8192 B
    __shared__ int      s_gs[64];
    __shared__ float    s_fa[32], s_fb[32];
    __shared__ int      s_ia[32];
    __shared__ int      sh_k, sh_rem;
    __shared__ unsigned sh_pref;
    __shared__ float    sh_lcpos;
    __shared__ bool     s_last;

    // stage mine bits early (long-latency gmem loads in flight)
    #pragma unroll
    for (int j = 0; j < 9; j++) {
        int i = tid + j * 1024;
        if (i < P) s_bits[i] = __float_as_uint(g_mine[b * P + i]);
    }

    // reduce k_main partials (CPB=69 entries -> warps 0..2)
    float ll = 0.f, lc = 0.f; int np = 0;
    if (tid < CPB) {
        int idx = b * CPB + tid;
        ll = g_part_lossl[idx]; lc = g_part_lcpos[idx]; np = g_part_npos[idx];
    }
    #pragma unroll
    for (int s = 16; s > 0; s >>= 1) {
        ll += __shfl_xor_sync(0xffffffffu, ll, s);
        lc += __shfl_xor_sync(0xffffffffu, lc, s);
        np += __shfl_xor_sync(0xffffffffu, np, s);
    }
    if (lane == 0) { s_fa[warp] = ll; s_fb[warp] = lc; s_ia[warp] = np; }
    __syncthreads();
    if (tid == 0) {
        s_last = false;
        float tll = 0.f, tlc = 0.f; int tnp = 0;
        #pragma unroll
        for (int w = 0; w < 3; w++) { tll += s_fa[w]; tlc += s_fb[w]; tnp += s_ia[w]; }
        g_lossl_b[b] = tll;
        g_npos_b[b]  = tnp;
        sh_lcpos = tlc;
        int k = 3 * tnp; if (k > P - 1) k = P - 1;
        sh_k = k;
        sh_rem = k;
        sh_pref = 0u;
    }
    __syncthreads();

    int k = sh_k;
    if (k > 0) {
        const int shifts[3]    = {21, 10, 0};
        const unsigned msks[3] = {0x00000000u, 0xFFE00000u, 0xFFFFFC00u};
        const int nbuck[3]     = {2048, 2048, 1024};

        for (int lev = 0; lev < 3; lev++) {
            int nb = nbuck[lev];
            for (int i = tid; i < nb; i += 1024) s_hist[i] = 0;
            __syncthreads();
            unsigned msk = msks[lev], pref = sh_pref;
            int sh = shifts[lev];
            unsigned bmask = (unsigned)(nb - 1);
            #pragma unroll
            for (int j = 0; j < 9; j++) {
                int i = tid + j * 1024;
                if (i < P) {
                    unsigned x = s_bits[i];
                    if ((x & msk) == pref)
                        atomicAdd(&s_hist[(x >> sh) & bmask], 1);
                }
            }
            __syncthreads();
            int ng = nb >> 5;
            if (tid < ng) {
                int s = 0;
                #pragma unroll
                for (int j = 0; j < 32; j++) s += s_hist[tid * 32 + j];
                s_gs[tid] = s;
            }
            __syncthreads();

            // warp-parallel selection (warp 0 only)
            if (tid < 32) {
                int rem = sh_rem;
                int g, remAfter;
                if (ng == 64) {
                    int suf1 = warp_suffix(s_gs[32 + lane], lane);
                    int tot1 = __shfl_sync(0xffffffffu, suf1, 0);
                    int suf0 = warp_suffix(s_gs[lane], lane);
                    unsigned m1 = __ballot_sync(0xffffffffu, suf1 >= rem);
                    if (m1) {
                        int l = 31 - __clz(m1);
                        g = 32 + l;
                        remAfter = (l == 31) ? 0 : __shfl_sync(0xffffffffu, suf1, l + 1);
                    } else {
                        unsigned m0 = __ballot_sync(0xffffffffu, (suf0 + tot1) >= rem);
                        int l = m0 ? (31 - __clz(m0)) : 0;
                        g = l;
                        remAfter = ((l == 31) ? 0 : __shfl_sync(0xffffffffu, suf0, l + 1)) + tot1;
                    }
                } else {
                    int suf = warp_suffix(s_gs[lane], lane);
                    unsigned m = __ballot_sync(0xffffffffu, suf >= rem);
                    int l = m ? (31 - __clz(m)) : 0;
                    g = l;
                    remAfter = (l == 31) ? 0 : __shfl_sync(0xffffffffu, suf, l + 1);
                }
                int rem2 = rem - remAfter;
                int sufh = warp_suffix(s_hist[g * 32 + lane], lane);
                unsigned mh = __ballot_sync(0xffffffffu, sufh >= rem2);
                int j = mh ? (31 - __clz(mh)) : 0;
                int after = (j == 31) ? 0 : __shfl_sync(0xffffffffu, sufh, j + 1);
                if (lane == 0) {
                    sh_rem = rem2 - after;
                    sh_pref = sh_pref | (((unsigned)(g * 32 + j)) << sh);
                }
            }
            __syncthreads();
        }

        unsigned vk = sh_pref;
        int cg = 0; float sg = 0.f;
        #pragma unroll
        for (int j = 0; j < 9; j++) {
            int i = tid + j * 1024;
            if (i < P) {
                unsigned x = s_bits[i];
                if (x > vk) { cg++; sg += __uint_as_float(x); }
            }
        }
        #pragma unroll
        for (int s = 16; s > 0; s >>= 1) {
            cg += __shfl_xor_sync(0xffffffffu, cg, s);
            sg += __shfl_xor_sync(0xffffffffu, sg, s);
        }
        if (lane == 0) { s_ia[warp] = cg; s_fa[warp] = sg; }
        __syncthreads();
        if (tid == 0) {
            int g = 0; float s = 0.f;
            #pragma unroll
            for (int w = 0; w < 32; w++) { g += s_ia[w]; s += s_fa[w]; }
            float lneg = s + (float)(k - g) * __uint_as_float(vk);
            g_lossc_b[b] = sh_lcpos + lneg;
        }
    } else {
        if (tid == 0) g_lossc_b[b] = sh_lcpos;
    }

    // ---- fused final combine: last arriving block reduces all batches ----
    if (tid == 0) {
        __threadfence();                       // publish g_loss*_b, g_npos_b
        int old = atomicAdd(&g_ctr_neg, 1);
        s_last = (old == B - 1);
    }
    __syncthreads();
    if (s_last) {
        __threadfence();                       // acquire others' writes
        float fl = 0.f, fc = 0.f; int fn = 0;
        if (tid < B) { fl = g_lossl_b[tid]; fc = g_lossc_b[tid]; fn = g_npos_b[tid]; }
        #pragma unroll
        for (int s = 16; s > 0; s >>= 1) {
            fl += __shfl_xor_sync(0xffffffffu, fl, s);
            fc += __shfl_xor_sync(0xffffffffu, fc, s);
            fn += __shfl_xor_sync(0xffffffffu, fn, s);
        }
        if (lane == 0 && warp < 2) { s_fa[warp] = fl; s_fb[warp] = fc; s_ia[warp] = fn; }
        __syncthreads();
        if (tid == 0) {
            float fN = (float)(s_ia[0] + s_ia[1]);
            out[0] = (s_fa[0] + s_fa[1]) / fN + (s_fb[0] + s_fb[1]) / fN;
            g_ctr_neg = 0;                     // reset for next replay
        }
    }
}

// ---------------- launch ----------------
extern "C" void kernel_launch(void* const* d_in, const int* in_sizes, int n_in,
                              void* d_out, int out_size) {
    const float* loc     = (const float*)d_in[0];   // (B,P,4)
    const float* conf    = (const float*)d_in[1];   // (B,P,NC)
    const float* priors  = (const float*)d_in[2];   // (P,4)
    const float* targets = (const float*)d_in[3];   // (B,NOBJ,5)
    float* out = (float*)d_out;

    k_match<<<dim3(MBX, B), 256>>>(priors, targets);
    k_main<<<B * CPB, RPB>>>(loc, conf, priors, targets);
    k_negred<<<B, 1024>>>(out);
}

// round 13
// speedup vs baseline: 1.4566x; 1.0090x over previous
#include <cuda_runtime.h>
#include <math.h>

#define B 64
#define P 8732
#define NOBJ 16
#define NC 81
#define THRESH 0.5f
#define RPB 128                 // conf rows per block in k_main
#define CPB 69                  // ceil(P/RPB)
#define NPART (B*CPB)

// ---------------- scratch (device globals; no allocs allowed) ----------------
__device__ float              g_overlap[B*P];   // unforced best IoU per prior
__device__ int                g_tidx[B*P];      // unforced best truth per prior
__device__ float              g_lc[B*P];        // lse - conf[ct] per prior (unforced)
__device__ unsigned long long g_bestprior[B*NOBJ];   // zero at load; negred restores zeros

__device__ float g_part_lossl[NPART];
__device__ float g_part_lcpos[NPART];
__device__ int   g_part_npos[NPART];

__device__ float g_lossl_b[B];
__device__ float g_lossc_b[B];
__device__ int   g_npos_b[B];

__device__ int g_ctr_neg;       // zero at load; last block resets

__device__ __forceinline__ float smooth_l1(float x) {
    float ax = fabsf(x);
    return (ax < 1.0f) ? 0.5f * x * x : ax - 0.5f;
}

__device__ __forceinline__ float enc_loss(float4 pr, const float* tr, float4 ld) {
    float gcx = ((tr[0] + tr[2]) * 0.5f - pr.x) / (0.1f * pr.z);
    float gcy = ((tr[1] + tr[3]) * 0.5f - pr.y) / (0.1f * pr.w);
    float gw  = __logf((tr[2] - tr[0]) / pr.z) * 5.0f;
    float gh  = __logf((tr[3] - tr[1]) / pr.w) * 5.0f;
    return smooth_l1(ld.x - gcx) + smooth_l1(ld.y - gcy)
         + smooth_l1(ld.z - gw)  + smooth_l1(ld.w - gh);
}

__device__ __forceinline__ int warp_suffix(int x, int lane) {
    #pragma unroll
    for (int s = 1; s < 32; s <<= 1) {
        int v = __shfl_down_sync(0xffffffffu, x, s);
        if (lane + s < 32) x += v;
    }
    return x;   // x[lane] = sum_{j>=lane} input[j]
}

// ---------------- kernel 1: fused matching + main loss ----------------------
// grid B*CPB, block 128 (thread per prior). Matching IoU work hides under the
// conf staging DRAM latency; per-truth argmax via REDUX + atomicMax.
__global__ void __launch_bounds__(RPB) k_main(const float* __restrict__ loc,
                                              const float* __restrict__ conf,
                                              const float* __restrict__ priors,
                                              const float* __restrict__ targets) {
    int blk = blockIdx.x;
    int b   = blk / CPB;
    int c   = blk % CPB;
    int p0  = c * RPB;
    int nrows = (p0 + RPB <= P) ? RPB : (P - p0);

    __shared__ float s_conf[RPB * NC];      // 41472 B
    __shared__ float s_t[NOBJ * 5];
    __shared__ unsigned long long s_wkey[4][NOBJ];
    __shared__ float s_ll[4], s_lc[4];
    __shared__ int   s_np[4];

    const float* base = conf + ((size_t)b * P + p0) * NC;
    int tid = threadIdx.x;
    int lane = tid & 31, warp = tid >> 5;

    if (tid < NOBJ * 5) s_t[tid] = targets[b * NOBJ * 5 + tid];

    // ---- conf staging: EXACT proven scalar unrolled pattern ----
    if (nrows == RPB) {
        #pragma unroll
        for (int j = 0; j < NC; j++)
            s_conf[tid + j * RPB] = __ldg(base + tid + j * RPB);
    } else {
        int total = nrows * NC;
        for (int i = tid; i < total; i += RPB)
            s_conf[i] = __ldg(base + i);
    }
    __syncthreads();

    // ---- matching: 16 IoUs + per-prior argmax + per-truth warp argmax ----
    bool valid = (tid < nrows);
    int p = p0 + tid;
    int pbase = p0 + warp * 32;

    float px1 = 0.f, py1 = 0.f, px2 = 0.f, py2 = 0.f, pa = 0.f;
    float4 pr4 = make_float4(1.f, 1.f, 1.f, 1.f);
    if (valid) {
        pr4 = *(const float4*)(priors + p * 4);
        px1 = pr4.x - pr4.z * 0.5f; py1 = pr4.y - pr4.w * 0.5f;
        px2 = pr4.x + pr4.z * 0.5f; py2 = pr4.y + pr4.w * 0.5f;
        pa  = (px2 - px1) * (py2 - py1);
    }

    float bestv = -1.0f; int besti = 0;
    #pragma unroll
    for (int t = 0; t < NOBJ; t++) {
        float tx1 = s_t[t*5+0], ty1 = s_t[t*5+1], tx2 = s_t[t*5+2], ty2 = s_t[t*5+3];
        float ix1 = fmaxf(tx1, px1), iy1 = fmaxf(ty1, py1);
        float ix2 = fminf(tx2, px2), iy2 = fminf(ty2, py2);
        float iw = fmaxf(ix2 - ix1, 0.f), ih = fmaxf(iy2 - iy1, 0.f);
        float inter = iw * ih;
        float ta = (tx2 - tx1) * (ty2 - ty1);
        float iou = inter / (ta + pa - inter);
        if (valid && iou > bestv) { bestv = iou; besti = t; }

        unsigned bits = valid ? __float_as_uint(iou) : 0u;
        unsigned wmax = __reduce_max_sync(0xffffffffu, bits);
        unsigned mask = __ballot_sync(0xffffffffu, valid && (bits == wmax));
        if (lane == 0) {
            unsigned long long key = 0ULL;
            if (mask) {
                int src = __ffs(mask) - 1;           // lowest lane = smallest p
                unsigned wp = (unsigned)(pbase + src);
                key = (((unsigned long long)wmax) << 32) |
                      (unsigned long long)(0xFFFFFFFFu - wp);
            }
            s_wkey[warp][t] = key;
        }
    }

    // ---- per-prior loss (UNFORCED; negred fixup corrects forced priors) ----
    float lossl = 0.f, lcpos = 0.f; int np = 0;
    if (valid) {
        const float* row = s_conf + tid * NC;
        float sum = 0.f;
        #pragma unroll
        for (int j = 0; j < NC; j++) sum += __expf(row[j]);
        float lse = __logf(sum);

        bool pos = (bestv >= THRESH);
        int  ct = 0;
        if (pos) ct = (int)s_t[besti * 5 + 4] + 1;

        float lc = lse - row[ct];
        g_overlap[b * P + p] = bestv;
        g_tidx[b * P + p]    = besti;
        g_lc[b * P + p]      = lc;

        if (pos) {
            np = 1; lcpos = lc;
            lossl = enc_loss(pr4, s_t + besti * 5,
                             *(const float4*)(loc + ((size_t)b * P + p) * 4));
        }
    }

    __syncthreads();
    if (tid < NOBJ) {
        unsigned long long k = 0ULL;
        #pragma unroll
        for (int w = 0; w < 4; w++) {
            unsigned long long v = s_wkey[w][tid];
            if (v > k) k = v;
        }
        atomicMax(&g_bestprior[b * NOBJ + tid], k);
    }

    #pragma unroll
    for (int s = 16; s > 0; s >>= 1) {
        lossl += __shfl_xor_sync(0xffffffffu, lossl, s);
        lcpos += __shfl_xor_sync(0xffffffffu, lcpos, s);
        np    += __shfl_xor_sync(0xffffffffu, np, s);
    }
    if (lane == 0) { s_ll[warp] = lossl; s_lc[warp] = lcpos; s_np[warp] = np; }
    __syncthreads();
    if (tid == 0) {
        float a = 0.f, bb = 0.f; int n = 0;
        #pragma unroll
        for (int w = 0; w < 4; w++) { a += s_ll[w]; bb += s_lc[w]; n += s_np[w]; }
        g_part_lossl[blk] = a;
        g_part_lcpos[blk] = bb;
        g_part_npos[blk]  = n;
    }
}

// ---------------- kernel 2: force-fixup + reduce + neg mining + final --------
// grid B, block 1024.
__global__ void __launch_bounds__(1024) k_negred(const float* __restrict__ loc,
                                                 const float* __restrict__ conf,
                                                 const float* __restrict__ priors,
                                                 const float* __restrict__ targets,
                                                 float* __restrict__ out) {
    int b = blockIdx.x;
    int tid = threadIdx.x, lane = tid & 31, warp = tid >> 5;

    __shared__ unsigned s_bits[P];          // 34928 B
    __shared__ int      s_hist[2048];       // 8192 B
    __shared__ int      s_gs[64];
    __shared__ float    s_fa[32], s_fb[32];
    __shared__ int      s_ia[32];
    __shared__ int      sh_k, sh_rem, sh_np;
    __shared__ unsigned sh_pref;
    __shared__ float    sh_lcpos, sh_lossl;
    __shared__ float    sh_lcd, sh_lld;
    __shared__ int      sh_npd;
    __shared__ bool     s_last;

    // stage mine bits: pos (ov>=0.5) -> 0 else lc bits (lc >= 0 always)
    #pragma unroll
    for (int j = 0; j < 9; j++) {
        int i = tid + j * 1024;
        if (i < P) {
            float ov = g_overlap[b * P + i];
            float lc = g_lc[b * P + i];
            s_bits[i] = (ov >= THRESH) ? 0u : __float_as_uint(lc);
        }
    }

    // reduce k_main partials (CPB=69 entries -> warps 0..2)
    float ll = 0.f, lc = 0.f; int np = 0;
    if (tid < CPB) {
        int idx = b * CPB + tid;
        ll = g_part_lossl[idx]; lc = g_part_lcpos[idx]; np = g_part_npos[idx];
    }
    #pragma unroll
    for (int s = 16; s > 0; s >>= 1) {
        ll += __shfl_xor_sync(0xffffffffu, ll, s);
        lc += __shfl_xor_sync(0xffffffffu, lc, s);
        np += __shfl_xor_sync(0xffffffffu, np, s);
    }
    if (lane == 0) { s_fa[warp] = ll; s_fb[warp] = lc; s_ia[warp] = np; }
    __syncthreads();
    if (tid == 0) {
        s_last = false;
        float tll = 0.f, tlc = 0.f; int tnp = 0;
        #pragma unroll
        for (int w = 0; w < 3; w++) { tll += s_fa[w]; tlc += s_fb[w]; tnp += s_ia[w]; }
        sh_lossl = tll; sh_lcpos = tlc; sh_np = tnp;
    }
    __syncthreads();   // s_bits staged + sh_* ready

    // ---- force fixup: lanes 0..15 of warp 0, one per truth j ----
    if (tid < NOBJ) {
        int j = tid;
        unsigned long long key = g_bestprior[b * NOBJ + j];
        g_bestprior[b * NOBJ + j] = 0ULL;          // reset for next replay
        unsigned pp = 0xFFFFFFFFu - (unsigned)(key & 0xFFFFFFFFull);

        unsigned peers = __match_any_sync(0xFFFFu, pp);
        bool owner = (j == 31 - __clz(peers));     // highest j wins (last set)

        int npd = 0; float lcd = 0.f, lld = 0.f;
        if (owner) {
            size_t gi = (size_t)b * P + pp;
            float ov_old = g_overlap[gi];
            int   t_old  = g_tidx[gi];
            bool  old_pos = (ov_old >= THRESH);
            float lcv = g_lc[gi];

            if (!old_pos) npd = 1;
            s_bits[pp] = 0u;                       // forced -> pos -> mine 0

            const float* crow = conf + gi * NC;
            int ct_old = old_pos ? (int)targets[(b*NOBJ + t_old)*5 + 4] + 1 : 0;
            float lse = lcv + __ldg(crow + ct_old);
            int ct_new = (int)targets[(b*NOBJ + j)*5 + 4] + 1;
            float lc_new = lse - __ldg(crow + ct_new);
            lcd = lc_new - (old_pos ? lcv : 0.f);

            float4 pr = *(const float4*)(priors + pp * 4);
            float4 ld = *(const float4*)(loc + gi * 4);
            float l_new = enc_loss(pr, targets + (b*NOBJ + j)*5, ld);
            float l_old = old_pos ? enc_loss(pr, targets + (b*NOBJ + t_old)*5, ld) : 0.f;
            lld = l_new - l_old;
        }
        // deterministic 16-lane reduce
        #pragma unroll
        for (int s = 8; s > 0; s >>= 1) {
            npd += __shfl_down_sync(0xFFFFu, npd, s);
            lcd += __shfl_down_sync(0xFFFFu, lcd, s);
            lld += __shfl_down_sync(0xFFFFu, lld, s);
        }
        if (j == 0) { sh_npd = npd; sh_lcd = lcd; sh_lld = lld; }
    }
    __syncthreads();

    if (tid == 0) {
        int tnp = sh_np + sh_npd;
        g_lossl_b[b] = sh_lossl + sh_lld;
        g_npos_b[b]  = tnp;
        sh_lcpos = sh_lcpos + sh_lcd;
        int k = 3 * tnp; if (k > P - 1) k = P - 1;
        sh_k = k; sh_rem = k; sh_pref = 0u;
    }
    __syncthreads();

    int k = sh_k;
    if (k > 0) {
        const int shifts[3]    = {21, 10, 0};
        const unsigned msks[3] = {0x00000000u, 0xFFE00000u, 0xFFFFFC00u};
        const int nbuck[3]     = {2048, 2048, 1024};

        for (int lev = 0; lev < 3; lev++) {
            int nb = nbuck[lev];
            for (int i = tid; i < nb; i += 1024) s_hist[i] = 0;
            __syncthreads();
            unsigned msk = msks[lev], pref = sh_pref;
            int sh = shifts[lev];
            unsigned bmask = (unsigned)(nb - 1);
            #pragma unroll
            for (int j = 0; j < 9; j++) {
                int i = tid + j * 1024;
                if (i < P) {
                    unsigned x = s_bits[i];
                    if ((x & msk) == pref)
                        atomicAdd(&s_hist[(x >> sh) & bmask], 1);
                }
            }
            __syncthreads();
            int ng = nb >> 5;
            if (tid < ng) {
                int s = 0;
                #pragma unroll
                for (int j = 0; j < 32; j++) s += s_hist[tid * 32 + j];
                s_gs[tid] = s;
            }
            __syncthreads();

            if (tid < 32) {
                int rem = sh_rem;
                int g, remAfter;
                if (ng == 64) {
                    int suf1 = warp_suffix(s_gs[32 + lane], lane);
                    int tot1 = __shfl_sync(0xffffffffu, suf1, 0);
                    int suf0 = warp_suffix(s_gs[lane], lane);
                    unsigned m1 = __ballot_sync(0xffffffffu, suf1 >= rem);
                    if (m1) {
                        int l = 31 - __clz(m1);
                        g = 32 + l;
                        remAfter = (l == 31) ? 0 : __shfl_sync(0xffffffffu, suf1, l + 1);
                    } else {
                        unsigned m0 = __ballot_sync(0xffffffffu, (suf0 + tot1) >= rem);
                        int l = m0 ? (31 - __clz(m0)) : 0;
                        g = l;
                        remAfter = ((l == 31) ? 0 : __shfl_sync(0xffffffffu, suf0, l + 1)) + tot1;
                    }
                } else {
                    int suf = warp_suffix(s_gs[lane], lane);
                    unsigned m = __ballot_sync(0xffffffffu, suf >= rem);
                    int l = m ? (31 - __clz(m)) : 0;
                    g = l;
                    remAfter = (l == 31) ? 0 : __shfl_sync(0xffffffffu, suf, l + 1);
                }
                int rem2 = rem - remAfter;
                int sufh = warp_suffix(s_hist[g * 32 + lane], lane);
                unsigned mh = __ballot_sync(0xffffffffu, sufh >= rem2);
                int j = mh ? (31 - __clz(mh)) : 0;
                int after = (j == 31) ? 0 : __shfl_sync(0xffffffffu, sufh, j + 1);
                if (lane == 0) {
                    sh_rem = rem2 - after;
                    sh_pref = sh_pref | (((unsigned)(g * 32 + j)) << sh);
                }
            }
            __syncthreads();
        }

        unsigned vk = sh_pref;
        int cg = 0; float sg = 0.f;
        #pragma unroll
        for (int j = 0; j < 9; j++) {
            int i = tid + j * 1024;
            if (i < P) {
                unsigned x = s_bits[i];
                if (x > vk) { cg++; sg += __uint_as_float(x); }
            }
        }
        #pragma unroll
        for (int s = 16; s > 0; s >>= 1) {
            cg += __shfl_xor_sync(0xffffffffu, cg, s);
            sg += __shfl_xor_sync(0xffffffffu, sg, s);
        }
        if (lane == 0) { s_ia[warp] = cg; s_fa[warp] = sg; }
        __syncthreads();
        if (tid == 0) {
            int g = 0; float s = 0.f;
            #pragma unroll
            for (int w = 0; w < 32; w++) { g += s_ia[w]; s += s_fa[w]; }
            float lneg = s + (float)(k - g) * __uint_as_float(vk);
            g_lossc_b[b] = sh_lcpos + lneg;
        }
    } else {
        if (tid == 0) g_lossc_b[b] = sh_lcpos;
    }

    // ---- fused final combine: last arriving block reduces all batches ----
    if (tid == 0) {
        __threadfence();
        int old = atomicAdd(&g_ctr_neg, 1);
        s_last = (old == B - 1);
    }
    __syncthreads();
    if (s_last) {
        __threadfence();
        float fl = 0.f, fc = 0.f; int fn = 0;
        if (tid < B) { fl = g_lossl_b[tid]; fc = g_lossc_b[tid]; fn = g_npos_b[tid]; }
        #pragma unroll
        for (int s = 16; s > 0; s >>= 1) {
            fl += __shfl_xor_sync(0xffffffffu, fl, s);
            fc += __shfl_xor_sync(0xffffffffu, fc, s);
            fn += __shfl_xor_sync(0xffffffffu, fn, s);
        }
        if (lane == 0 && warp < 2) { s_fa[warp] = fl; s_fb[warp] = fc; s_ia[warp] = fn; }
        __syncthreads();
        if (tid == 0) {
            float fN = (float)(s_ia[0] + s_ia[1]);
            out[0] = (s_fa[0] + s_fa[1]) / fN + (s_fb[0] + s_fb[1]) / fN;
            g_ctr_neg = 0;
        }
    }
}

// ---------------- launch ----------------
extern "C" void kernel_launch(void* const* d_in, const int* in_sizes, int n_in,
                              void* d_out, int out_size) {
    const float* loc     = (const float*)d_in[0];   // (B,P,4)
    const float* conf    = (const float*)d_in[1];   // (B,P,NC)
    const float* priors  = (const float*)d_in[2];   // (P,4)
    const float* targets = (const float*)d_in[3];   // (B,NOBJ,5)
    float* out = (float*)d_out;

    k_main<<<B * CPB, RPB>>>(loc, conf, priors, targets);
    k_negred<<<B, 1024>>>(loc, conf, priors, targets, out);
}